// round 1
// baseline (speedup 1.0000x reference)
#include <cuda_runtime.h>
#include <cstddef>

#define BB 32
#define SS 576
#define DD 768
#define HH 12
#define HDD 64
#define MTOK (BB*SS)               // 18432
#define OUT_ELEMS (BB*SS*DD)       // 14155776
#define ATTN_ELEMS (BB*HH*SS*SS)   // 127401984
#define SCALE 0.125f               // 64^-0.5

// ---- scratch (static device globals; no runtime allocation) ----
__device__ float g_q[OUT_ELEMS];
__device__ float g_k[OUT_ELEMS];
__device__ float g_v[OUT_ELEMS];
__device__ float g_ctx[OUT_ELEMS];
__device__ float g_attn_fallback[ATTN_ELEMS];  // used only if d_out lacks attn region

// ============================================================================
// GEMM: C[M,N] = A[M,K] @ W^T + bias,  W is [N,K] row-major (torch Linear).
// BM=128, BN=128, BK=16, 256 threads, 8x8 per-thread register tile.
// M,N,K must be multiples of tile dims (true here: 18432, 768, 768).
// ============================================================================
__global__ __launch_bounds__(256) void gemm_bias(
    const float* __restrict__ A, const float* __restrict__ W,
    const float* __restrict__ bias, float* __restrict__ C,
    int M, int N, int K)
{
    __shared__ float As[16 * 128];   // [k][m]
    __shared__ float Bs[16 * 128];   // [k][n]

    const int tid  = threadIdx.x;
    const int tRow = tid >> 4;       // 0..15
    const int tCol = tid & 15;       // 0..15
    const int m0 = blockIdx.y * 128;
    const int n0 = blockIdx.x * 128;

    float acc[8][8];
    #pragma unroll
    for (int i = 0; i < 8; i++)
        #pragma unroll
        for (int j = 0; j < 8; j++) acc[i][j] = 0.f;

    for (int k0 = 0; k0 < K; k0 += 16) {
        // load A tile (128x16) transposed into As[k][m]
        #pragma unroll
        for (int i = 0; i < 2; i++) {
            int idx = tid + i * 256;         // float4 index in [0,512)
            int row = idx >> 2;              // 4 float4 per row
            int c4  = idx & 3;
            float4 v = *(const float4*)&A[(size_t)(m0 + row) * K + k0 + c4 * 4];
            As[(c4*4+0)*128 + row] = v.x;
            As[(c4*4+1)*128 + row] = v.y;
            As[(c4*4+2)*128 + row] = v.z;
            As[(c4*4+3)*128 + row] = v.w;
        }
        // load W tile: Bs[k][n] = W[(n0+n)*K + k0+k]
        #pragma unroll
        for (int i = 0; i < 2; i++) {
            int idx = tid + i * 256;
            int n  = idx >> 2;
            int c4 = idx & 3;
            float4 v = *(const float4*)&W[(size_t)(n0 + n) * K + k0 + c4 * 4];
            Bs[(c4*4+0)*128 + n] = v.x;
            Bs[(c4*4+1)*128 + n] = v.y;
            Bs[(c4*4+2)*128 + n] = v.z;
            Bs[(c4*4+3)*128 + n] = v.w;
        }
        __syncthreads();

        #pragma unroll
        for (int k = 0; k < 16; k++) {
            float4 a0 = *(const float4*)&As[k*128 + tRow*8];
            float4 a1 = *(const float4*)&As[k*128 + tRow*8 + 4];
            float4 b0 = *(const float4*)&Bs[k*128 + tCol*8];
            float4 b1 = *(const float4*)&Bs[k*128 + tCol*8 + 4];
            float av[8] = {a0.x,a0.y,a0.z,a0.w,a1.x,a1.y,a1.z,a1.w};
            float bv[8] = {b0.x,b0.y,b0.z,b0.w,b1.x,b1.y,b1.z,b1.w};
            #pragma unroll
            for (int i = 0; i < 8; i++)
                #pragma unroll
                for (int j = 0; j < 8; j++)
                    acc[i][j] = fmaf(av[i], bv[j], acc[i][j]);
        }
        __syncthreads();
    }

    #pragma unroll
    for (int i = 0; i < 8; i++) {
        int row = m0 + tRow*8 + i;
        #pragma unroll
        for (int j = 0; j < 8; j += 4) {
            int col = n0 + tCol*8 + j;
            float4 o;
            o.x = acc[i][j+0] + bias[col+0];
            o.y = acc[i][j+1] + bias[col+1];
            o.z = acc[i][j+2] + bias[col+2];
            o.w = acc[i][j+3] + bias[col+3];
            *(float4*)&C[(size_t)row * N + col] = o;
        }
    }
}

// ============================================================================
// Fused scores + softmax per (b, h, 64-query tile).
// Keeps full 64x576 score strip in dynamic SMEM (176 KB); writes normalized
// attn to global. Q/K tiles stored d-major (transposed) for conflict-free
// float4 smem reads in the 4x4 register-tiled QK^T inner loop.
// ============================================================================
__global__ __launch_bounds__(256) void attn_scores_softmax(
    const float* __restrict__ Q, const float* __restrict__ K,
    float* __restrict__ attn)
{
    extern __shared__ float smem[];
    float* qsT = smem;               // [64][64]  (d-major)
    float* ksT = smem + 4096;        // [64][64]
    float* sc  = smem + 8192;        // [64][576]

    const int qt = blockIdx.x, h = blockIdx.y, b = blockIdx.z;
    const int s0 = qt * 64;
    const int tid  = threadIdx.x;
    const int tRow = tid >> 4;
    const int tCol = tid & 15;

    // load Q tile transposed: qsT[d][qi]
    #pragma unroll
    for (int i = 0; i < 4; i++) {
        int idx = tid + i * 256;     // float4 idx in [0,1024)
        int qi = idx >> 4;           // 16 float4 per row of 64 d
        int d4 = idx & 15;
        float4 v = *(const float4*)&Q[((size_t)(b*SS + s0 + qi)) * DD + h*HDD + d4*4];
        qsT[(d4*4+0)*64 + qi] = v.x;
        qsT[(d4*4+1)*64 + qi] = v.y;
        qsT[(d4*4+2)*64 + qi] = v.z;
        qsT[(d4*4+3)*64 + qi] = v.w;
    }

    for (int kt = 0; kt < SS/64; kt++) {
        __syncthreads();  // ksT reuse safety (and covers qsT readiness on kt=0)
        #pragma unroll
        for (int i = 0; i < 4; i++) {
            int idx = tid + i * 256;
            int kj = idx >> 4;
            int d4 = idx & 15;
            float4 v = *(const float4*)&K[((size_t)(b*SS + kt*64 + kj)) * DD + h*HDD + d4*4];
            ksT[(d4*4+0)*64 + kj] = v.x;
            ksT[(d4*4+1)*64 + kj] = v.y;
            ksT[(d4*4+2)*64 + kj] = v.z;
            ksT[(d4*4+3)*64 + kj] = v.w;
        }
        __syncthreads();

        float acc[4][4];
        #pragma unroll
        for (int i = 0; i < 4; i++)
            #pragma unroll
            for (int j = 0; j < 4; j++) acc[i][j] = 0.f;

        #pragma unroll 16
        for (int d = 0; d < 64; d++) {
            float4 a = *(const float4*)&qsT[d*64 + tRow*4];
            float4 bb = *(const float4*)&ksT[d*64 + tCol*4];
            float av[4] = {a.x,a.y,a.z,a.w};
            float bv[4] = {bb.x,bb.y,bb.z,bb.w};
            #pragma unroll
            for (int i = 0; i < 4; i++)
                #pragma unroll
                for (int j = 0; j < 4; j++)
                    acc[i][j] = fmaf(av[i], bv[j], acc[i][j]);
        }

        #pragma unroll
        for (int i = 0; i < 4; i++) {
            float4 o;
            o.x = acc[i][0]*SCALE; o.y = acc[i][1]*SCALE;
            o.z = acc[i][2]*SCALE; o.w = acc[i][3]*SCALE;
            *(float4*)&sc[(tRow*4+i)*SS + kt*64 + tCol*4] = o;
        }
    }
    __syncthreads();

    // softmax: 8 warps x 8 rows each
    const int warp = tid >> 5, lane = tid & 31;
    for (int r = warp*8; r < warp*8 + 8; r++) {
        float mx = -1e30f;
        for (int j = lane; j < SS; j += 32) mx = fmaxf(mx, sc[r*SS + j]);
        #pragma unroll
        for (int o = 16; o; o >>= 1) mx = fmaxf(mx, __shfl_xor_sync(0xffffffffu, mx, o));
        float sum = 0.f;
        for (int j = lane; j < SS; j += 32) {
            float e = __expf(sc[r*SS + j] - mx);
            sc[r*SS + j] = e;
            sum += e;
        }
        #pragma unroll
        for (int o = 16; o; o >>= 1) sum += __shfl_xor_sync(0xffffffffu, sum, o);
        float inv = 1.f / sum;
        float* dst = attn + (((size_t)b*HH + h)*SS + s0 + r) * (size_t)SS;
        for (int j = lane; j < SS; j += 32) dst[j] = sc[r*SS + j] * inv;
    }
}

// ============================================================================
// ctx = attn @ V per (b, h, 64-query tile). BM=64, BN=64(=HD), BK=32 over 576.
// ============================================================================
__global__ __launch_bounds__(256) void attn_ctx(
    const float* __restrict__ attn, const float* __restrict__ V,
    float* __restrict__ ctx)
{
    __shared__ float AsT[32 * 64];   // [k][qi]
    __shared__ float Bs[32 * 64];    // [k][n]

    const int qt = blockIdx.x, h = blockIdx.y, b = blockIdx.z;
    const int s0 = qt * 64;
    const int tid  = threadIdx.x;
    const int tRow = tid >> 4;
    const int tCol = tid & 15;

    const float* arow = attn + (((size_t)b*HH + h)*SS + s0) * (size_t)SS;

    float acc[4][4];
    #pragma unroll
    for (int i = 0; i < 4; i++)
        #pragma unroll
        for (int j = 0; j < 4; j++) acc[i][j] = 0.f;

    for (int k0 = 0; k0 < SS; k0 += 32) {
        #pragma unroll
        for (int i = 0; i < 2; i++) {
            int idx = tid + i * 256;   // float4 idx in [0,512)
            int qi = idx >> 3;         // 8 float4 per 32-col row
            int c4 = idx & 7;
            float4 v = *(const float4*)&arow[(size_t)qi*SS + k0 + c4*4];
            AsT[(c4*4+0)*64 + qi] = v.x;
            AsT[(c4*4+1)*64 + qi] = v.y;
            AsT[(c4*4+2)*64 + qi] = v.z;
            AsT[(c4*4+3)*64 + qi] = v.w;
        }
        #pragma unroll
        for (int i = 0; i < 2; i++) {
            int idx = tid + i * 256;
            int kk = idx >> 4;         // 16 float4 per 64-col row
            int n4 = idx & 15;
            float4 v = *(const float4*)&V[((size_t)(b*SS + k0 + kk))*DD + h*HDD + n4*4];
            *(float4*)&Bs[kk*64 + n4*4] = v;
        }
        __syncthreads();

        #pragma unroll
        for (int k = 0; k < 32; k++) {
            float4 a  = *(const float4*)&AsT[k*64 + tRow*4];
            float4 bb = *(const float4*)&Bs[k*64 + tCol*4];
            float av[4] = {a.x,a.y,a.z,a.w};
            float bv[4] = {bb.x,bb.y,bb.z,bb.w};
            #pragma unroll
            for (int i = 0; i < 4; i++)
                #pragma unroll
                for (int j = 0; j < 4; j++)
                    acc[i][j] = fmaf(av[i], bv[j], acc[i][j]);
        }
        __syncthreads();
    }

    #pragma unroll
    for (int i = 0; i < 4; i++) {
        float4 o = {acc[i][0], acc[i][1], acc[i][2], acc[i][3]};
        *(float4*)&ctx[((size_t)(b*SS + s0 + tRow*4 + i))*DD + h*HDD + tCol*4] = o;
    }
}

// ============================================================================
extern "C" void kernel_launch(void* const* d_in, const int* in_sizes, int n_in,
                              void* d_out, int out_size)
{
    const float* x  = (const float*)d_in[0];
    const float* Wq = (const float*)d_in[1];
    const float* bq = (const float*)d_in[2];
    const float* Wk = (const float*)d_in[3];
    const float* bk = (const float*)d_in[4];
    const float* Wv = (const float*)d_in[5];
    const float* bv = (const float*)d_in[6];
    const float* Wo = (const float*)d_in[7];
    const float* bo = (const float*)d_in[8];

    float* out = (float*)d_out;
    // reference returns (out, attn); harness flattens tuple in order.
    float* attn;
    if (out_size >= OUT_ELEMS + ATTN_ELEMS) {
        attn = out + OUT_ELEMS;
    } else {
        // attn not part of output: use scratch
        void* p; cudaGetSymbolAddress(&p, g_attn_fallback);
        attn = (float*)p;
    }

    float *q, *k, *v, *ctx;
    { void* p; cudaGetSymbolAddress(&p, g_q);   q   = (float*)p; }
    { void* p; cudaGetSymbolAddress(&p, g_k);   k   = (float*)p; }
    { void* p; cudaGetSymbolAddress(&p, g_v);   v   = (float*)p; }
    { void* p; cudaGetSymbolAddress(&p, g_ctx); ctx = (float*)p; }

    const dim3 gProj(DD/128, MTOK/128);   // (6, 144)
    gemm_bias<<<gProj, 256>>>(x, Wq, bq, q, MTOK, DD, DD);
    gemm_bias<<<gProj, 256>>>(x, Wk, bk, k, MTOK, DD, DD);
    gemm_bias<<<gProj, 256>>>(x, Wv, bv, v, MTOK, DD, DD);

    const int smem_bytes = (4096 + 4096 + 64*SS) * (int)sizeof(float); // 180224
    cudaFuncSetAttribute(attn_scores_softmax,
                         cudaFuncAttributeMaxDynamicSharedMemorySize, smem_bytes);
    const dim3 gAttn(SS/64, HH, BB);      // (9, 12, 32)
    attn_scores_softmax<<<gAttn, 256, smem_bytes>>>(q, k, attn);
    attn_ctx<<<gAttn, 256>>>(attn, v, ctx);

    gemm_bias<<<gProj, 256>>>(ctx, Wo, bo, out, MTOK, DD, DD);
}

// round 2
// speedup vs baseline: 2.4626x; 2.4626x over previous
#include <cuda_runtime.h>
#include <cstdint>
#include <cstddef>

#define BB 32
#define SS 576
#define DD 768
#define HH 12
#define HDD 64
#define MTOK (BB*SS)               // 18432
#define OUT_ELEMS (BB*SS*DD)       // 14155776
#define ATTN_ELEMS (BB*HH*SS*SS)   // 127401984
#define SCALE 0.125f

// ---- scratch (static device globals; no runtime allocation) ----
__device__ float g_q[OUT_ELEMS];
__device__ float g_k[OUT_ELEMS];
__device__ float g_v[OUT_ELEMS];
__device__ float g_ctx[OUT_ELEMS];
__device__ float g_xr[OUT_ELEMS];          // tf32-rounded x
__device__ float g_wq[DD*DD], g_wk[DD*DD], g_wv[DD*DD], g_wo[DD*DD];
__device__ float g_attn_fallback[ATTN_ELEMS];

// ---------------------------------------------------------------------------
__device__ __forceinline__ float rna_tf32(float x) {
    unsigned u;
    asm("cvt.rna.tf32.f32 %0, %1;" : "=r"(u) : "f"(x));
    return __uint_as_float(u);
}

__device__ __forceinline__ void mma_tf32(float c[4],
    uint32_t a0, uint32_t a1, uint32_t a2, uint32_t a3,
    uint32_t b0, uint32_t b1)
{
    asm volatile(
        "mma.sync.aligned.m16n8k8.row.col.f32.tf32.tf32.f32 "
        "{%0,%1,%2,%3}, {%4,%5,%6,%7}, {%8,%9}, {%0,%1,%2,%3};"
        : "+f"(c[0]), "+f"(c[1]), "+f"(c[2]), "+f"(c[3])
        : "r"(a0), "r"(a1), "r"(a2), "r"(a3), "r"(b0), "r"(b1));
}

__device__ __forceinline__ void cpa16(void* dst, const void* src) {
    uint32_t d = (uint32_t)__cvta_generic_to_shared(dst);
    asm volatile("cp.async.cg.shared.global [%0], [%1], 16;\n"
                 :: "r"(d), "l"(src));
}

// ---------------------------------------------------------------------------
// elementwise tf32 rounding pass (float4, grid-stride), n divisible by 4
__global__ void round_tf32_kernel(const float* __restrict__ in,
                                  float* __restrict__ out, int n4)
{
    for (int i = blockIdx.x * blockDim.x + threadIdx.x; i < n4;
         i += gridDim.x * blockDim.x) {
        float4 v = ((const float4*)in)[i];
        v.x = rna_tf32(v.x); v.y = rna_tf32(v.y);
        v.z = rna_tf32(v.z); v.w = rna_tf32(v.w);
        ((float4*)out)[i] = v;
    }
}

// ---------------------------------------------------------------------------
// GEMM: C[M,N] = A[M,K] @ W^T + bias.  A,W already tf32-rounded fp32.
// BM=128, BN=128, BK=16, 256 threads, tf32 mma, cp.async double buffer.
// ---------------------------------------------------------------------------
__global__ __launch_bounds__(256) void gemm_tf32(
    const float* __restrict__ A, const float* __restrict__ W,
    const float* __restrict__ bias, float* __restrict__ C,
    int M, int N, int K)
{
    __shared__ float As[2][128*20];
    __shared__ float Bs[2][128*20];

    const int tid = threadIdx.x;
    const int m0 = blockIdx.y * 128;
    const int n0 = blockIdx.x * 128;
    const int warp = tid >> 5;
    const int lane = tid & 31;
    const int g = lane >> 2;      // group 0..7
    const int t = lane & 3;       // thread-in-group
    const int warpm = warp >> 2;  // 0..1  (64 rows each)
    const int warpn = warp & 3;   // 0..3  (32 cols each)

    float acc[4][4][4];
    #pragma unroll
    for (int i = 0; i < 4; i++)
        #pragma unroll
        for (int j = 0; j < 4; j++)
            #pragma unroll
            for (int r = 0; r < 4; r++) acc[i][j][r] = 0.f;

    auto load_stage = [&](int st, int k0) {
        #pragma unroll
        for (int i = 0; i < 2; i++) {
            int c = tid + i * 256;
            int row = c >> 2, seg = c & 3;
            cpa16(&As[st][row*20 + seg*4],
                  &A[(size_t)(m0 + row) * K + k0 + seg*4]);
        }
        #pragma unroll
        for (int i = 0; i < 2; i++) {
            int c = tid + i * 256;
            int row = c >> 2, seg = c & 3;
            cpa16(&Bs[st][row*20 + seg*4],
                  &W[(size_t)(n0 + row) * K + k0 + seg*4]);
        }
    };

    const int iters = K / 16;
    load_stage(0, 0);
    asm volatile("cp.async.commit_group;\n" ::);

    for (int it = 0; it < iters; ++it) {
        int s = it & 1;
        if (it + 1 < iters) load_stage(s ^ 1, (it + 1) * 16);
        asm volatile("cp.async.commit_group;\n" ::);
        asm volatile("cp.async.wait_group 1;\n" ::);
        __syncthreads();

        const float* as = As[s];
        const float* bs = Bs[s];
        #pragma unroll
        for (int ks = 0; ks < 2; ks++) {
            int k = ks * 8;
            uint32_t af[4][4];
            #pragma unroll
            for (int ms = 0; ms < 4; ms++) {
                const float* p = as + (warpm*64 + ms*16 + g) * 20 + k + t;
                af[ms][0] = __float_as_uint(p[0]);
                af[ms][1] = __float_as_uint(p[8*20]);
                af[ms][2] = __float_as_uint(p[4]);
                af[ms][3] = __float_as_uint(p[8*20 + 4]);
            }
            #pragma unroll
            for (int ns = 0; ns < 4; ns++) {
                const float* p = bs + (warpn*32 + ns*8 + g) * 20 + k + t;
                uint32_t b0 = __float_as_uint(p[0]);
                uint32_t b1 = __float_as_uint(p[4]);
                #pragma unroll
                for (int ms = 0; ms < 4; ms++)
                    mma_tf32(acc[ms][ns], af[ms][0], af[ms][1], af[ms][2],
                             af[ms][3], b0, b1);
            }
        }
        __syncthreads();
    }

    #pragma unroll
    for (int ms = 0; ms < 4; ms++) {
        int row0 = m0 + warpm*64 + ms*16 + g;
        #pragma unroll
        for (int ns = 0; ns < 4; ns++) {
            int col = n0 + warpn*32 + ns*8 + 2*t;
            float b0v = bias[col], b1v = bias[col + 1];
            float2 v0 = {acc[ms][ns][0] + b0v, acc[ms][ns][1] + b1v};
            *(float2*)&C[(size_t)row0 * N + col] = v0;
            float2 v1 = {acc[ms][ns][2] + b0v, acc[ms][ns][3] + b1v};
            *(float2*)&C[(size_t)(row0 + 8) * N + col] = v1;
        }
    }
}

// ---------------------------------------------------------------------------
// Fused scores + softmax per (b, h, 64-query tile), tf32 mma for QK^T.
// ---------------------------------------------------------------------------
#define SCQ 68      // Q/K smem row stride
#define SCS 580     // score strip row stride
#define SCORE_SMEM_FLOATS (2*64*SCQ + 64*SCS)

__global__ __launch_bounds__(256) void attn_scores_softmax(
    const float* __restrict__ Q, const float* __restrict__ K,
    float* __restrict__ attn)
{
    extern __shared__ float smem[];
    float* qs = smem;                    // [64][SCQ]
    float* ks = smem + 64*SCQ;           // [64][SCQ]
    float* sc = smem + 2*64*SCQ;         // [64][SCS]

    const int qt = blockIdx.x, h = blockIdx.y, b = blockIdx.z;
    const int s0 = qt * 64;
    const int tid = threadIdx.x;
    const int warp = tid >> 5;
    const int lane = tid & 31;
    const int g = lane >> 2, t = lane & 3;
    const int warpm = warp >> 2;   // 0..1 (32 rows)
    const int warpn = warp & 3;    // 0..3 (16 cols)

    // load Q tile (rounded to tf32)
    #pragma unroll
    for (int i = 0; i < 4; i++) {
        int idx = tid + i * 256;
        int qi = idx >> 4, d4 = idx & 15;
        float4 v = *(const float4*)&Q[((size_t)(b*SS + s0 + qi))*DD + h*HDD + d4*4];
        float* p = qs + qi*SCQ + d4*4;
        p[0] = rna_tf32(v.x); p[1] = rna_tf32(v.y);
        p[2] = rna_tf32(v.z); p[3] = rna_tf32(v.w);
    }

    for (int kt = 0; kt < SS/64; kt++) {
        __syncthreads();
        #pragma unroll
        for (int i = 0; i < 4; i++) {
            int idx = tid + i * 256;
            int kj = idx >> 4, d4 = idx & 15;
            float4 v = *(const float4*)&K[((size_t)(b*SS + kt*64 + kj))*DD + h*HDD + d4*4];
            float* p = ks + kj*SCQ + d4*4;
            p[0] = rna_tf32(v.x); p[1] = rna_tf32(v.y);
            p[2] = rna_tf32(v.z); p[3] = rna_tf32(v.w);
        }
        __syncthreads();

        float acc[2][2][4];
        #pragma unroll
        for (int i = 0; i < 2; i++)
            #pragma unroll
            for (int j = 0; j < 2; j++)
                #pragma unroll
                for (int r = 0; r < 4; r++) acc[i][j][r] = 0.f;

        #pragma unroll
        for (int kk = 0; kk < 8; kk++) {
            int k = kk * 8;
            uint32_t af[2][4];
            #pragma unroll
            for (int ms = 0; ms < 2; ms++) {
                const float* p = qs + (warpm*32 + ms*16 + g)*SCQ + k + t;
                af[ms][0] = __float_as_uint(p[0]);
                af[ms][1] = __float_as_uint(p[8*SCQ]);
                af[ms][2] = __float_as_uint(p[4]);
                af[ms][3] = __float_as_uint(p[8*SCQ + 4]);
            }
            #pragma unroll
            for (int ns = 0; ns < 2; ns++) {
                const float* p = ks + (warpn*16 + ns*8 + g)*SCQ + k + t;
                uint32_t b0 = __float_as_uint(p[0]);
                uint32_t b1 = __float_as_uint(p[4]);
                #pragma unroll
                for (int ms = 0; ms < 2; ms++)
                    mma_tf32(acc[ms][ns], af[ms][0], af[ms][1], af[ms][2],
                             af[ms][3], b0, b1);
            }
        }

        #pragma unroll
        for (int ms = 0; ms < 2; ms++) {
            int row = warpm*32 + ms*16 + g;
            #pragma unroll
            for (int ns = 0; ns < 2; ns++) {
                int col = kt*64 + warpn*16 + ns*8 + 2*t;
                float2 v0 = {acc[ms][ns][0]*SCALE, acc[ms][ns][1]*SCALE};
                *(float2*)&sc[row*SCS + col] = v0;
                float2 v1 = {acc[ms][ns][2]*SCALE, acc[ms][ns][3]*SCALE};
                *(float2*)&sc[(row+8)*SCS + col] = v1;
            }
        }
    }
    __syncthreads();

    // softmax: 8 warps x 8 rows
    for (int r = warp*8; r < warp*8 + 8; r++) {
        float mx = -1e30f;
        for (int j = lane; j < SS; j += 32) mx = fmaxf(mx, sc[r*SCS + j]);
        #pragma unroll
        for (int o = 16; o; o >>= 1) mx = fmaxf(mx, __shfl_xor_sync(0xffffffffu, mx, o));
        float sum = 0.f;
        for (int j = lane; j < SS; j += 32) {
            float e = __expf(sc[r*SCS + j] - mx);
            sc[r*SCS + j] = e;
            sum += e;
        }
        #pragma unroll
        for (int o = 16; o; o >>= 1) sum += __shfl_xor_sync(0xffffffffu, sum, o);
        float inv = 1.f / sum;
        float* dst = attn + (((size_t)b*HH + h)*SS + s0 + r) * (size_t)SS;
        for (int j = lane; j < SS; j += 32) dst[j] = sc[r*SCS + j] * inv;
    }
}

// ---------------------------------------------------------------------------
// ctx = attn @ V per (b, h, 64-query tile).  tf32 mma, K tiled by 32.
// Stores ctx tf32-rounded (feeds final GEMM raw).
// ---------------------------------------------------------------------------
__global__ __launch_bounds__(256) void attn_ctx(
    const float* __restrict__ attn, const float* __restrict__ V,
    float* __restrict__ ctx)
{
    __shared__ float As[64*36];   // attn tile [m][k], stride 36
    __shared__ float Vs[32*72];   // V tile [k][n], stride 72

    const int qt = blockIdx.x, h = blockIdx.y, b = blockIdx.z;
    const int s0 = qt * 64;
    const int tid = threadIdx.x;
    const int warp = tid >> 5;
    const int lane = tid & 31;
    const int g = lane >> 2, t = lane & 3;
    const int warpm = warp >> 2;  // 0..1
    const int warpn = warp & 3;   // 0..3

    const float* arow = attn + (((size_t)b*HH + h)*SS + s0) * (size_t)SS;

    float acc[2][2][4];
    #pragma unroll
    for (int i = 0; i < 2; i++)
        #pragma unroll
        for (int j = 0; j < 2; j++)
            #pragma unroll
            for (int r = 0; r < 4; r++) acc[i][j][r] = 0.f;

    for (int k0 = 0; k0 < SS; k0 += 32) {
        __syncthreads();
        #pragma unroll
        for (int i = 0; i < 2; i++) {
            int c = tid + i * 256;
            int row = c >> 3, seg = c & 7;
            float4 v = *(const float4*)&arow[(size_t)row*SS + k0 + seg*4];
            float* p = As + row*36 + seg*4;
            p[0] = rna_tf32(v.x); p[1] = rna_tf32(v.y);
            p[2] = rna_tf32(v.z); p[3] = rna_tf32(v.w);
        }
        #pragma unroll
        for (int i = 0; i < 2; i++) {
            int c = tid + i * 256;
            int row = c >> 4, seg = c & 15;
            float4 v = *(const float4*)&V[((size_t)(b*SS + k0 + row))*DD + h*HDD + seg*4];
            float* p = Vs + row*72 + seg*4;
            p[0] = rna_tf32(v.x); p[1] = rna_tf32(v.y);
            p[2] = rna_tf32(v.z); p[3] = rna_tf32(v.w);
        }
        __syncthreads();

        #pragma unroll
        for (int kk = 0; kk < 4; kk++) {
            int k = kk * 8;
            uint32_t af[2][4];
            #pragma unroll
            for (int ms = 0; ms < 2; ms++) {
                const float* p = As + (warpm*32 + ms*16 + g)*36 + k + t;
                af[ms][0] = __float_as_uint(p[0]);
                af[ms][1] = __float_as_uint(p[8*36]);
                af[ms][2] = __float_as_uint(p[4]);
                af[ms][3] = __float_as_uint(p[8*36 + 4]);
            }
            #pragma unroll
            for (int ns = 0; ns < 2; ns++) {
                int nb = warpn*16 + ns*8;
                uint32_t b0 = __float_as_uint(Vs[(k + t)*72 + nb + g]);
                uint32_t b1 = __float_as_uint(Vs[(k + t + 4)*72 + nb + g]);
                #pragma unroll
                for (int ms = 0; ms < 2; ms++)
                    mma_tf32(acc[ms][ns], af[ms][0], af[ms][1], af[ms][2],
                             af[ms][3], b0, b1);
            }
        }
    }

    #pragma unroll
    for (int ms = 0; ms < 2; ms++) {
        int row = warpm*32 + ms*16 + g;
        #pragma unroll
        for (int ns = 0; ns < 2; ns++) {
            int col = warpn*16 + ns*8 + 2*t;
            float2 v0 = {rna_tf32(acc[ms][ns][0]), rna_tf32(acc[ms][ns][1])};
            *(float2*)&ctx[((size_t)(b*SS + s0 + row))*DD + h*HDD + col] = v0;
            float2 v1 = {rna_tf32(acc[ms][ns][2]), rna_tf32(acc[ms][ns][3])};
            *(float2*)&ctx[((size_t)(b*SS + s0 + row + 8))*DD + h*HDD + col] = v1;
        }
    }
}

// ===========================================================================
extern "C" void kernel_launch(void* const* d_in, const int* in_sizes, int n_in,
                              void* d_out, int out_size)
{
    const float* x  = (const float*)d_in[0];
    const float* Wq = (const float*)d_in[1];
    const float* bq = (const float*)d_in[2];
    const float* Wk = (const float*)d_in[3];
    const float* bk = (const float*)d_in[4];
    const float* Wv = (const float*)d_in[5];
    const float* bv = (const float*)d_in[6];
    const float* Wo = (const float*)d_in[7];
    const float* bo = (const float*)d_in[8];

    float* out = (float*)d_out;
    float* attn;
    if (out_size >= OUT_ELEMS + ATTN_ELEMS) {
        attn = out + OUT_ELEMS;
    } else {
        void* p; cudaGetSymbolAddress(&p, g_attn_fallback);
        attn = (float*)p;
    }

    float *q, *k, *v, *ctx, *xr, *wq, *wk, *wv, *wo;
    { void* p; cudaGetSymbolAddress(&p, g_q);   q   = (float*)p; }
    { void* p; cudaGetSymbolAddress(&p, g_k);   k   = (float*)p; }
    { void* p; cudaGetSymbolAddress(&p, g_v);   v   = (float*)p; }
    { void* p; cudaGetSymbolAddress(&p, g_ctx); ctx = (float*)p; }
    { void* p; cudaGetSymbolAddress(&p, g_xr);  xr  = (float*)p; }
    { void* p; cudaGetSymbolAddress(&p, g_wq);  wq  = (float*)p; }
    { void* p; cudaGetSymbolAddress(&p, g_wk);  wk  = (float*)p; }
    { void* p; cudaGetSymbolAddress(&p, g_wv);  wv  = (float*)p; }
    { void* p; cudaGetSymbolAddress(&p, g_wo);  wo  = (float*)p; }

    // tf32 pre-rounding passes
    round_tf32_kernel<<<1184, 256>>>(x, xr, OUT_ELEMS/4);
    round_tf32_kernel<<<576, 256>>>(Wq, wq, (DD*DD)/4);
    round_tf32_kernel<<<576, 256>>>(Wk, wk, (DD*DD)/4);
    round_tf32_kernel<<<576, 256>>>(Wv, wv, (DD*DD)/4);
    round_tf32_kernel<<<576, 256>>>(Wo, wo, (DD*DD)/4);

    const dim3 gProj(DD/128, MTOK/128);   // (6, 144)
    gemm_tf32<<<gProj, 256>>>(xr, wq, bq, q, MTOK, DD, DD);
    gemm_tf32<<<gProj, 256>>>(xr, wk, bk, k, MTOK, DD, DD);
    gemm_tf32<<<gProj, 256>>>(xr, wv, bv, v, MTOK, DD, DD);

    const int smem_bytes = SCORE_SMEM_FLOATS * (int)sizeof(float);
    cudaFuncSetAttribute(attn_scores_softmax,
                         cudaFuncAttributeMaxDynamicSharedMemorySize, smem_bytes);
    const dim3 gAttn(SS/64, HH, BB);      // (9, 12, 32)
    attn_scores_softmax<<<gAttn, 256, smem_bytes>>>(q, k, attn);
    attn_ctx<<<gAttn, 256>>>(attn, v, ctx);

    gemm_tf32<<<gProj, 256>>>(ctx, wo, bo, out, MTOK, DD, DD);
}